// round 2
// baseline (speedup 1.0000x reference)
#include <cuda_runtime.h>
#include <cstdint>

#define B 8
#define A 110484
#define C 90
#define NN (A * C)          /* 9,943,560 per image */
#define N4 (NN / 4)         /* 2,485,890 */
#define TOPK 5000
#define MAXOUT 100
#define CAND_CAP 16384
#define BINS 4096
#define IOU_T 0.5f

/* ------------------------- scratch (static, no allocs) ------------------ */
__device__ unsigned int       g_hist[B][BINS];
__device__ unsigned int       g_thresh[B];
__device__ int                g_cnt[B];
__device__ unsigned long long g_cand[B][CAND_CAP];
__device__ float4             g_boxes[B][TOPK];
__device__ float              g_scores[B][TOPK];
__device__ int                g_cls[B][TOPK];
__device__ float              g_maxc[B];

/* order-preserving float<->uint key */
__device__ __forceinline__ unsigned int fkey(float f) {
    unsigned int u = __float_as_uint(f);
    return (u & 0x80000000u) ? ~u : (u | 0x80000000u);
}
__device__ __forceinline__ float finv(unsigned int k) {
    unsigned int u = (k & 0x80000000u) ? (k ^ 0x80000000u) : ~k;
    return __uint_as_float(u);
}

/* ------------------------------ init ------------------------------------ */
__global__ void k_init() {
    int t = blockIdx.x * blockDim.x + threadIdx.x;
    if (t < B) g_cnt[t] = 0;
    unsigned int* h = &g_hist[0][0];
    for (int i = t; i < B * BINS; i += gridDim.x * blockDim.x) h[i] = 0;
}

/* --------------------------- pass 1: histogram -------------------------- */
__global__ void k_hist(const float* __restrict__ cls) {
    __shared__ unsigned int h[BINS];
    const int b = blockIdx.y;
    for (int i = threadIdx.x; i < BINS; i += blockDim.x) h[i] = 0;
    __syncthreads();
    const float4* p = (const float4*)(cls + (size_t)b * NN);
    for (int i = blockIdx.x * blockDim.x + threadIdx.x; i < N4;
         i += gridDim.x * blockDim.x) {
        float4 v = p[i];
        atomicAdd(&h[fkey(v.x) >> 20], 1u);
        atomicAdd(&h[fkey(v.y) >> 20], 1u);
        atomicAdd(&h[fkey(v.z) >> 20], 1u);
        atomicAdd(&h[fkey(v.w) >> 20], 1u);
    }
    __syncthreads();
    for (int i = threadIdx.x; i < BINS; i += blockDim.x)
        if (h[i]) atomicAdd(&g_hist[b][i], h[i]);
}

/* ----------------------- pass 2: find threshold bin ---------------------- */
__global__ void k_thresh() {
    const int b = blockIdx.x;
    __shared__ unsigned int h[BINS];
    __shared__ unsigned int csum[256];
    for (int i = threadIdx.x; i < BINS; i += blockDim.x) h[i] = g_hist[b][i];
    __syncthreads();
    if (threadIdx.x < 256) {
        unsigned int s = 0;
        for (int k = 0; k < 16; k++) s += h[threadIdx.x * 16 + k];
        csum[threadIdx.x] = s;
    }
    __syncthreads();
    if (threadIdx.x == 0) {
        unsigned int acc = 0;
        int T = 0;
        for (int ch = 255; ch >= 0; ch--) {
            if (acc + csum[ch] >= TOPK) {
                for (int bin = ch * 16 + 15; bin >= ch * 16; bin--) {
                    acc += h[bin];
                    if (acc >= TOPK) { T = bin; break; }
                }
                break;
            }
            acc += csum[ch];
        }
        g_thresh[b] = ((unsigned int)T) << 20;
    }
}

/* -------------------------- pass 3: collect ------------------------------ */
__global__ void k_collect(const float* __restrict__ cls) {
    const int b = blockIdx.y;
    const unsigned int th = g_thresh[b];
    const float4* p = (const float4*)(cls + (size_t)b * NN);
    for (int i = blockIdx.x * blockDim.x + threadIdx.x; i < N4;
         i += gridDim.x * blockDim.x) {
        float4 v = p[i];
        unsigned int base = 4u * (unsigned int)i;
        unsigned int k0 = fkey(v.x), k1 = fkey(v.y), k2 = fkey(v.z), k3 = fkey(v.w);
        if (k0 >= th) {
            int pos = atomicAdd(&g_cnt[b], 1);
            if (pos < CAND_CAP)
                g_cand[b][pos] = ((unsigned long long)k0 << 32) | (0xFFFFFFFFu - (base + 0u));
        }
        if (k1 >= th) {
            int pos = atomicAdd(&g_cnt[b], 1);
            if (pos < CAND_CAP)
                g_cand[b][pos] = ((unsigned long long)k1 << 32) | (0xFFFFFFFFu - (base + 1u));
        }
        if (k2 >= th) {
            int pos = atomicAdd(&g_cnt[b], 1);
            if (pos < CAND_CAP)
                g_cand[b][pos] = ((unsigned long long)k2 << 32) | (0xFFFFFFFFu - (base + 2u));
        }
        if (k3 >= th) {
            int pos = atomicAdd(&g_cnt[b], 1);
            if (pos < CAND_CAP)
                g_cand[b][pos] = ((unsigned long long)k3 << 32) | (0xFFFFFFFFu - (base + 3u));
        }
    }
}

/* ---------------- pass 4: per-image bitonic sort + decode ---------------- */
__global__ void k_sort_decode(const float* __restrict__ box_out,
                              const float* __restrict__ anchors) {
    extern __shared__ unsigned long long s[];
    const int b = blockIdx.x;
    const int tid = threadIdx.x;
    int cnt = g_cnt[b];
    if (cnt > CAND_CAP) cnt = CAND_CAP;
    const int nn = (cnt <= 8192) ? 8192 : 16384;

    for (int i = tid; i < nn; i += blockDim.x)
        s[i] = (i < cnt) ? g_cand[b][i] : 0ULL;
    __syncthreads();

    /* bitonic sort, descending */
    for (unsigned int k = 2; k <= (unsigned int)nn; k <<= 1) {
        for (unsigned int j = k >> 1; j > 0; j >>= 1) {
            for (int i = tid; i < nn; i += blockDim.x) {
                unsigned int ixj = (unsigned int)i ^ j;
                if (ixj > (unsigned int)i) {
                    bool up = ((i & k) == 0);
                    unsigned long long a = s[i], c2 = s[ixj];
                    bool sw = up ? (a < c2) : (a > c2);
                    if (sw) { s[i] = c2; s[ixj] = a; }
                }
            }
            __syncthreads();
        }
    }

    /* decode top-5000 */
    const float4* bo4 = (const float4*)box_out;
    const float4* an4 = (const float4*)anchors;
    float localmax = -1e30f;
    for (int i = tid; i < TOPK; i += blockDim.x) {
        unsigned long long kv = s[i];
        if (kv == 0ULL) {  /* defensive: fewer than TOPK candidates */
            g_boxes[b][i] = make_float4(0.f, 0.f, 0.f, 0.f);
            g_scores[b][i] = 0.f;
            g_cls[b][i] = 0;
            continue;
        }
        unsigned int key = (unsigned int)(kv >> 32);
        unsigned int idx = 0xFFFFFFFFu - (unsigned int)(kv & 0xFFFFFFFFu);
        float val = finv(key);
        unsigned int a = idx / (unsigned int)C;
        int cidx = (int)(idx - a * (unsigned int)C);
        float4 rc = bo4[(size_t)b * A + a];
        float4 an = an4[a];
        float ycA = (an.x + an.z) * 0.5f;
        float xcA = (an.y + an.w) * 0.5f;
        float ha = an.z - an.x;
        float wa = an.w - an.y;
        float w = expf(rc.w) * wa;
        float h = expf(rc.z) * ha;
        float yc = rc.x * ha + ycA;
        float xc = rc.y * wa + xcA;
        float4 box = make_float4(xc - w * 0.5f, yc - h * 0.5f,
                                 xc + w * 0.5f, yc + h * 0.5f);
        g_boxes[b][i] = box;
        g_scores[b][i] = 1.f / (1.f + expf(-val));
        g_cls[b][i] = cidx;
        float m = fmaxf(fmaxf(box.x, box.y), fmaxf(box.z, box.w));
        localmax = fmaxf(localmax, m);
    }
    __shared__ float red[1024];
    red[tid] = localmax;
    __syncthreads();
    for (int off = 512; off > 0; off >>= 1) {
        if (tid < off) red[tid] = fmaxf(red[tid], red[tid + off]);
        __syncthreads();
    }
    if (tid == 0) g_maxc[b] = red[0];
}

/* ---------------------- pass 5: greedy NMS + output ---------------------- */
__global__ void k_nms(const float* __restrict__ img_scale, float* __restrict__ out) {
    const int b = blockIdx.x;
    const int l = threadIdx.x; /* 32 threads: one warp per image */
    __shared__ float4 skb[MAXOUT + 32];
    __shared__ float ska[MAXOUT + 32];
    __shared__ float4 st_box[64];
    __shared__ float st_sc[64];
    __shared__ int st_cl[64];

    const float maxc1 = g_maxc[b] + 1.0f;
    const float scale = img_scale[b];
    int K = 0;

    for (int base = 0; base < TOPK && K < MAXOUT; base += 64) {
        int m = TOPK - base;
        if (m > 64) m = 64;
        for (int t = l; t < m; t += 32) {
            st_box[t] = g_boxes[b][base + t];
            st_sc[t] = g_scores[b][base + t];
            st_cl[t] = g_cls[b][base + t];
        }
        __syncwarp();
        for (int ii = 0; ii < m; ii++) {
            if (K >= MAXOUT) break;
            float4 bx = st_box[ii];
            int cidx = st_cl[ii];
            float off = (float)cidx * maxc1;
            float4 nb = make_float4(bx.x + off, bx.y + off, bx.z + off, bx.w + off);
            float areaC = (nb.z - nb.x) * (nb.w - nb.y);
            bool ov = false;
            for (int sidx = l; sidx < K; sidx += 32) {
                float4 kb = skb[sidx];
                float w = fminf(nb.z, kb.z) - fmaxf(nb.x, kb.x);
                float h = fminf(nb.w, kb.w) - fmaxf(nb.y, kb.y);
                w = fmaxf(w, 0.f);
                h = fmaxf(h, 0.f);
                float inter = w * h;
                if (inter > 0.f) {
                    float uni = areaC + ska[sidx] - inter;
                    if (inter / uni > IOU_T) ov = true;
                }
            }
            if (!__any_sync(0xffffffffu, ov)) {
                if (l == 0) {
                    skb[K] = nb;
                    ska[K] = areaC;
                    float* o = out + ((size_t)b * MAXOUT + K) * 6;
                    o[0] = bx.x * scale;
                    o[1] = bx.y * scale;
                    o[2] = bx.z * scale;
                    o[3] = bx.w * scale;
                    o[4] = st_sc[ii];
                    o[5] = (float)(cidx + 1);
                }
                K++;
                __syncwarp();
            }
        }
        __syncwarp();
    }
    /* pad invalid rows */
    for (int r = l; r < MAXOUT; r += 32) {
        if (r >= K) {
            float* o = out + ((size_t)b * MAXOUT + r) * 6;
            o[0] = 0.f; o[1] = 0.f; o[2] = 0.f; o[3] = 0.f;
            o[4] = 0.f; o[5] = -1.f;
        }
    }
}

/* ------------------------------ launcher -------------------------------- */
extern "C" void kernel_launch(void* const* d_in, const int* in_sizes, int n_in,
                              void* d_out, int out_size) {
    const float* cls = nullptr;
    const float* box = nullptr;
    const float* anc = nullptr;
    const float* scl = nullptr;
    for (int i = 0; i < n_in; i++) {
        long long sz = in_sizes[i];
        if (sz == (long long)B * NN) cls = (const float*)d_in[i];
        else if (sz == (long long)B * A * 4) box = (const float*)d_in[i];
        else if (sz == (long long)A * 4) anc = (const float*)d_in[i];
        else if (sz == B) scl = (const float*)d_in[i];
    }
    float* out = (float*)d_out;

    static bool attr_set = false;
    if (!attr_set) {
        cudaFuncSetAttribute(k_sort_decode,
                             cudaFuncAttributeMaxDynamicSharedMemorySize,
                             CAND_CAP * (int)sizeof(unsigned long long));
        attr_set = true;
    }

    k_init<<<32, 1024>>>();
    {
        dim3 grid(512, B);
        k_hist<<<grid, 256>>>(cls);
    }
    k_thresh<<<B, 1024>>>();
    {
        dim3 grid(512, B);
        k_collect<<<grid, 256>>>(cls);
    }
    k_sort_decode<<<B, 1024, CAND_CAP * sizeof(unsigned long long)>>>(box, anc);
    k_nms<<<B, 32>>>(scl, out);
}

// round 5
// speedup vs baseline: 1.4431x; 1.4431x over previous
#include <cuda_runtime.h>
#include <cstdint>

#define B 8
#define A 110484
#define C 90
#define NN (A * C)          /* 9,943,560 per image */
#define N4 (NN / 4)         /* 2,485,890 */
#define TOPK 5000
#define MAXOUT 100
#define CAND_CAP 32768
#define SORT_CAP 16384
#define IOU_T 0.5f

#define SPEC_F 3.0f
#define KEY0 0xC0400000u    /* fkey(3.0f) */
#define HBINS 1024
#define HSHIFT 13
#define FBINS 4096

/* ------------------------- scratch (static, no allocs) ------------------ */
__device__ unsigned int       g_hist[B][HBINS];   /* fine bins, keys >= 3.0 */
__device__ unsigned int       g_fhist[B][FBINS];  /* fallback full-range    */
__device__ unsigned int       g_thresh[B];
__device__ int                g_ok[B];
__device__ int                g_cnt[B];
__device__ unsigned long long g_cand[B][CAND_CAP];
__device__ float4             g_boxes[B][TOPK];
__device__ float              g_scores[B][TOPK];
__device__ int                g_cls[B][TOPK];
__device__ float              g_maxc[B];

/* order-preserving float<->uint key */
__device__ __forceinline__ unsigned int fkey(float f) {
    unsigned int u = __float_as_uint(f);
    return (u & 0x80000000u) ? ~u : (u | 0x80000000u);
}
__device__ __forceinline__ float finv(unsigned int k) {
    unsigned int u = (k & 0x80000000u) ? (k ^ 0x80000000u) : ~k;
    return __uint_as_float(u);
}

/* ------------------------------ init ------------------------------------ */
__global__ void k_init() {
    int t = blockIdx.x * blockDim.x + threadIdx.x;
    int stride = gridDim.x * blockDim.x;
    if (t < B) g_cnt[t] = 0;
    unsigned int* h = &g_hist[0][0];
    for (int i = t; i < B * HBINS; i += stride) h[i] = 0;
    unsigned int* fh = &g_fhist[0][0];
    for (int i = t; i < B * FBINS; i += stride) fh[i] = 0;
}

/* ------------- pass 1: fused speculative collect + fine hist ------------ */
__device__ __forceinline__ void proc_elem(float val, unsigned int eidx, int b) {
    if (val >= SPEC_F) {
        unsigned int key = __float_as_uint(val) | 0x80000000u; /* val>0 */
        unsigned int bin = (key - KEY0) >> HSHIFT;
        if (bin > HBINS - 1) bin = HBINS - 1;
        atomicAdd(&g_hist[b][bin], 1u);
        int pos = atomicAdd(&g_cnt[b], 1);
        if (pos < CAND_CAP)
            g_cand[b][pos] =
                ((unsigned long long)key << 32) | (0xFFFFFFFFu - eidx);
    }
}
__device__ __forceinline__ void proc_vec(float4 v, unsigned int i, int b) {
    unsigned int base = 4u * i;
    proc_elem(v.x, base + 0u, b);
    proc_elem(v.y, base + 1u, b);
    proc_elem(v.z, base + 2u, b);
    proc_elem(v.w, base + 3u, b);
}

__global__ void __launch_bounds__(256) k_main(const float* __restrict__ cls) {
    const int b = blockIdx.y;
    const float4* __restrict__ p = (const float4*)(cls + (size_t)b * NN);
    const unsigned int i0 = blockIdx.x * 1024u + threadIdx.x;
    float4 v0, v1, v2, v3;
    const float4 neg = make_float4(-1e30f, -1e30f, -1e30f, -1e30f);
    if ((blockIdx.x + 1) * 1024u <= (unsigned)N4) {
        v0 = p[i0];
        v1 = p[i0 + 256];
        v2 = p[i0 + 512];
        v3 = p[i0 + 768];
    } else {
        v0 = (i0       < (unsigned)N4) ? p[i0]       : neg;
        v1 = (i0 + 256 < (unsigned)N4) ? p[i0 + 256] : neg;
        v2 = (i0 + 512 < (unsigned)N4) ? p[i0 + 512] : neg;
        v3 = (i0 + 768 < (unsigned)N4) ? p[i0 + 768] : neg;
    }
    float m0 = fmaxf(fmaxf(v0.x, v0.y), fmaxf(v0.z, v0.w));
    float m1 = fmaxf(fmaxf(v1.x, v1.y), fmaxf(v1.z, v1.w));
    float m2 = fmaxf(fmaxf(v2.x, v2.y), fmaxf(v2.z, v2.w));
    float m3 = fmaxf(fmaxf(v3.x, v3.y), fmaxf(v3.z, v3.w));
    float m = fmaxf(fmaxf(m0, m1), fmaxf(m2, m3));
    if (m >= SPEC_F) {  /* ~2% of threads */
        proc_vec(v0, i0, b);
        proc_vec(v1, i0 + 256, b);
        proc_vec(v2, i0 + 512, b);
        proc_vec(v3, i0 + 768, b);
    }
}

/* -------------- pass 2: exact threshold from fine histogram -------------- */
__global__ void k_thresh() {
    const int b = blockIdx.x;
    __shared__ unsigned int h[HBINS];
    for (int i = threadIdx.x; i < HBINS; i += blockDim.x) h[i] = g_hist[b][i];
    __syncthreads();
    if (threadIdx.x == 0) {
        unsigned int acc = 0;
        int T = -1;
        for (int bin = HBINS - 1; bin >= 0; bin--) {
            acc += h[bin];
            if (acc >= TOPK) { T = bin; break; }
        }
        int cnt = g_cnt[b];
        int ok = (T >= 0) && (cnt <= CAND_CAP) && (acc <= SORT_CAP);
        g_ok[b] = ok;
        if (ok) g_thresh[b] = KEY0 + ((unsigned int)T << HSHIFT);
    }
}

/* ---------------- fallback chain (early-exits when spec ok) -------------- */
__global__ void k_fb_hist(const float* __restrict__ cls) {
    const int b = blockIdx.y;
    if (g_ok[b]) return;
    __shared__ unsigned int h[FBINS];
    for (int i = threadIdx.x; i < FBINS; i += blockDim.x) h[i] = 0;
    __syncthreads();
    const float4* p = (const float4*)(cls + (size_t)b * NN);
    for (int i = blockIdx.x * blockDim.x + threadIdx.x; i < N4;
         i += gridDim.x * blockDim.x) {
        float4 v = p[i];
        atomicAdd(&h[fkey(v.x) >> 20], 1u);
        atomicAdd(&h[fkey(v.y) >> 20], 1u);
        atomicAdd(&h[fkey(v.z) >> 20], 1u);
        atomicAdd(&h[fkey(v.w) >> 20], 1u);
    }
    __syncthreads();
    for (int i = threadIdx.x; i < FBINS; i += blockDim.x)
        if (h[i]) atomicAdd(&g_fhist[b][i], h[i]);
}

__global__ void k_fb_thresh() {
    const int b = blockIdx.x;
    if (g_ok[b]) return;
    __shared__ unsigned int h[FBINS];
    for (int i = threadIdx.x; i < FBINS; i += blockDim.x) h[i] = g_fhist[b][i];
    __syncthreads();
    if (threadIdx.x == 0) {
        unsigned int acc = 0;
        int T = 0;
        for (int bin = FBINS - 1; bin >= 0; bin--) {
            acc += h[bin];
            if (acc >= TOPK) { T = bin; break; }
        }
        g_thresh[b] = ((unsigned int)T) << 20;
        g_cnt[b] = 0;
    }
}

__global__ void k_fb_collect(const float* __restrict__ cls) {
    const int b = blockIdx.y;
    if (g_ok[b]) return;
    const unsigned int th = g_thresh[b];
    const float4* p = (const float4*)(cls + (size_t)b * NN);
    for (int i = blockIdx.x * blockDim.x + threadIdx.x; i < N4;
         i += gridDim.x * blockDim.x) {
        float4 v = p[i];
        unsigned int base = 4u * (unsigned int)i;
        unsigned int k0 = fkey(v.x), k1 = fkey(v.y), k2 = fkey(v.z), k3 = fkey(v.w);
        if (k0 >= th) {
            int pos = atomicAdd(&g_cnt[b], 1);
            if (pos < CAND_CAP)
                g_cand[b][pos] = ((unsigned long long)k0 << 32) | (0xFFFFFFFFu - (base + 0u));
        }
        if (k1 >= th) {
            int pos = atomicAdd(&g_cnt[b], 1);
            if (pos < CAND_CAP)
                g_cand[b][pos] = ((unsigned long long)k1 << 32) | (0xFFFFFFFFu - (base + 1u));
        }
        if (k2 >= th) {
            int pos = atomicAdd(&g_cnt[b], 1);
            if (pos < CAND_CAP)
                g_cand[b][pos] = ((unsigned long long)k2 << 32) | (0xFFFFFFFFu - (base + 2u));
        }
        if (k3 >= th) {
            int pos = atomicAdd(&g_cnt[b], 1);
            if (pos < CAND_CAP)
                g_cand[b][pos] = ((unsigned long long)k3 << 32) | (0xFFFFFFFFu - (base + 3u));
        }
    }
}

/* --------- pass 3: filter to exact superset + bitonic sort + decode ------ */
__global__ void k_sort_decode(const float* __restrict__ box_out,
                              const float* __restrict__ anchors) {
    extern __shared__ unsigned long long s[];
    const int b = blockIdx.x;
    const int tid = threadIdx.x;
    __shared__ int scnt;
    if (tid == 0) scnt = 0;
    __syncthreads();

    int cnt = g_cnt[b];
    if (cnt > CAND_CAP) cnt = CAND_CAP;
    const unsigned int th = g_thresh[b];
    for (int i = tid; i < cnt; i += blockDim.x) {
        unsigned long long kv = g_cand[b][i];
        if ((unsigned int)(kv >> 32) >= th) {
            int pos = atomicAdd(&scnt, 1);
            if (pos < SORT_CAP) s[pos] = kv;
        }
    }
    __syncthreads();
    int c2 = scnt;
    if (c2 > SORT_CAP) c2 = SORT_CAP;
    const int nn = (c2 <= 8192) ? 8192 : SORT_CAP;
    for (int i = c2 + tid; i < nn; i += blockDim.x) s[i] = 0ULL;
    __syncthreads();

    /* bitonic sort, descending */
    for (unsigned int k = 2; k <= (unsigned int)nn; k <<= 1) {
        for (unsigned int j = k >> 1; j > 0; j >>= 1) {
            for (int i = tid; i < nn; i += blockDim.x) {
                unsigned int ixj = (unsigned int)i ^ j;
                if (ixj > (unsigned int)i) {
                    bool up = ((i & k) == 0);
                    unsigned long long a = s[i], c = s[ixj];
                    bool sw = up ? (a < c) : (a > c);
                    if (sw) { s[i] = c; s[ixj] = a; }
                }
            }
            __syncthreads();
        }
    }

    /* decode top-5000 */
    const float4* bo4 = (const float4*)box_out;
    const float4* an4 = (const float4*)anchors;
    float localmax = -1e30f;
    for (int i = tid; i < TOPK; i += blockDim.x) {
        unsigned long long kv = s[i];
        if (kv == 0ULL) {
            g_boxes[b][i] = make_float4(0.f, 0.f, 0.f, 0.f);
            g_scores[b][i] = 0.f;
            g_cls[b][i] = 0;
            continue;
        }
        unsigned int key = (unsigned int)(kv >> 32);
        unsigned int idx = 0xFFFFFFFFu - (unsigned int)(kv & 0xFFFFFFFFu);
        float val = finv(key);
        unsigned int a = idx / (unsigned int)C;
        int cidx = (int)(idx - a * (unsigned int)C);
        float4 rc = bo4[(size_t)b * A + a];
        float4 an = an4[a];
        float ycA = (an.x + an.z) * 0.5f;
        float xcA = (an.y + an.w) * 0.5f;
        float ha = an.z - an.x;
        float wa = an.w - an.y;
        float w = expf(rc.w) * wa;
        float h = expf(rc.z) * ha;
        float yc = rc.x * ha + ycA;
        float xc = rc.y * wa + xcA;
        float4 box = make_float4(xc - w * 0.5f, yc - h * 0.5f,
                                 xc + w * 0.5f, yc + h * 0.5f);
        g_boxes[b][i] = box;
        g_scores[b][i] = 1.f / (1.f + expf(-val));
        g_cls[b][i] = cidx;
        float m = fmaxf(fmaxf(box.x, box.y), fmaxf(box.z, box.w));
        localmax = fmaxf(localmax, m);
    }
    __shared__ float red[1024];
    red[tid] = localmax;
    __syncthreads();
    for (int off = 512; off > 0; off >>= 1) {
        if (tid < off) red[tid] = fmaxf(red[tid], red[tid + off]);
        __syncthreads();
    }
    if (tid == 0) g_maxc[b] = red[0];
}

/* ---------------------- pass 4: greedy NMS + output ---------------------- */
__global__ void k_nms(const float* __restrict__ img_scale, float* __restrict__ out) {
    const int b = blockIdx.x;
    const int l = threadIdx.x; /* one warp per image */
    __shared__ float4 skb[MAXOUT + 32];
    __shared__ float ska[MAXOUT + 32];
    __shared__ float4 st_box[64];
    __shared__ float st_sc[64];
    __shared__ int st_cl[64];

    const float maxc1 = g_maxc[b] + 1.0f;
    const float scale = img_scale[b];
    int K = 0;

    for (int base = 0; base < TOPK && K < MAXOUT; base += 64) {
        int m = TOPK - base;
        if (m > 64) m = 64;
        for (int t = l; t < m; t += 32) {
            st_box[t] = g_boxes[b][base + t];
            st_sc[t] = g_scores[b][base + t];
            st_cl[t] = g_cls[b][base + t];
        }
        __syncwarp();
        for (int ii = 0; ii < m; ii++) {
            if (K >= MAXOUT) break;
            float4 bx = st_box[ii];
            int cidx = st_cl[ii];
            float off = (float)cidx * maxc1;
            float4 nb = make_float4(bx.x + off, bx.y + off, bx.z + off, bx.w + off);
            float areaC = (nb.z - nb.x) * (nb.w - nb.y);
            bool ov = false;
            for (int sidx = l; sidx < K; sidx += 32) {
                float4 kb = skb[sidx];
                float w = fminf(nb.z, kb.z) - fmaxf(nb.x, kb.x);
                float h = fminf(nb.w, kb.w) - fmaxf(nb.y, kb.y);
                w = fmaxf(w, 0.f);
                h = fmaxf(h, 0.f);
                float inter = w * h;
                if (inter > 0.f) {
                    float uni = areaC + ska[sidx] - inter;
                    if (inter / uni > IOU_T) ov = true;
                }
            }
            if (!__any_sync(0xffffffffu, ov)) {
                if (l == 0) {
                    skb[K] = nb;
                    ska[K] = areaC;
                    float* o = out + ((size_t)b * MAXOUT + K) * 6;
                    o[0] = bx.x * scale;
                    o[1] = bx.y * scale;
                    o[2] = bx.z * scale;
                    o[3] = bx.w * scale;
                    o[4] = st_sc[ii];
                    o[5] = (float)(cidx + 1);
                }
                K++;
                __syncwarp();
            }
        }
        __syncwarp();
    }
    for (int r = l; r < MAXOUT; r += 32) {
        if (r >= K) {
            float* o = out + ((size_t)b * MAXOUT + r) * 6;
            o[0] = 0.f; o[1] = 0.f; o[2] = 0.f; o[3] = 0.f;
            o[4] = 0.f; o[5] = -1.f;
        }
    }
}

/* ------------------------------ launcher -------------------------------- */
extern "C" void kernel_launch(void* const* d_in, const int* in_sizes, int n_in,
                              void* d_out, int out_size) {
    const float* cls = nullptr;
    const float* box = nullptr;
    const float* anc = nullptr;
    const float* scl = nullptr;
    for (int i = 0; i < n_in; i++) {
        long long sz = in_sizes[i];
        if (sz == (long long)B * NN) cls = (const float*)d_in[i];
        else if (sz == (long long)B * A * 4) box = (const float*)d_in[i];
        else if (sz == (long long)A * 4) anc = (const float*)d_in[i];
        else if (sz == B) scl = (const float*)d_in[i];
    }
    float* out = (float*)d_out;

    static bool attr_set = false;
    if (!attr_set) {
        cudaFuncSetAttribute(k_sort_decode,
                             cudaFuncAttributeMaxDynamicSharedMemorySize,
                             SORT_CAP * (int)sizeof(unsigned long long));
        attr_set = true;
    }

    k_init<<<64, 1024>>>();
    {
        dim3 grid((N4 + 1023) / 1024, B);
        k_main<<<grid, 256>>>(cls);
    }
    k_thresh<<<B, 256>>>();
    {
        dim3 grid(256, B);
        k_fb_hist<<<grid, 256>>>(cls);
    }
    k_fb_thresh<<<B, 1024>>>();
    {
        dim3 grid(256, B);
        k_fb_collect<<<grid, 256>>>(cls);
    }
    k_sort_decode<<<B, 1024, SORT_CAP * sizeof(unsigned long long)>>>(box, anc);
    k_nms<<<B, 32>>>(scl, out);
}

// round 6
// speedup vs baseline: 2.4016x; 1.6642x over previous
#include <cuda_runtime.h>
#include <cstdint>

#define B 8
#define A 110484
#define C 90
#define NN (A * C)          /* 9,943,560 per image */
#define N4 (NN / 4)         /* 2,485,890 */
#define TOPK 5000
#define MAXOUT 100
#define CAND_CAP 32768
#define SORT_CAP 16384
#define IOU_T 0.5f

#define SPEC_F 3.0f
#define KEY0 0xC0400000u    /* fkey(3.0f) */
#define HBINS 1024
#define HSHIFT 13
#define FBINS 4096
#define BINMAX 1024         /* per-bin sort capacity */

/* ------------------------- scratch (static, no allocs) ------------------ */
__device__ unsigned int       g_hist[B][HBINS];     /* fine bins, keys >= 3.0 */
__device__ unsigned int       g_fhist[B][FBINS];    /* fallback full-range    */
__device__ unsigned int       g_binstart[B][HBINS]; /* descending prefix      */
__device__ unsigned int       g_binoff[B][HBINS];   /* scatter cursors        */
__device__ unsigned int       g_thresh[B];
__device__ int                g_T[B];               /* threshold bin          */
__device__ int                g_ok[B];
__device__ int                g_cnt[B];
__device__ unsigned long long g_cand[B][CAND_CAP];
__device__ unsigned long long g_sorted[B][SORT_CAP];
__device__ float4             g_boxes[B][TOPK];
__device__ float              g_scores[B][TOPK];
__device__ int                g_cls[B][TOPK];
__device__ unsigned int       g_maxck[B];           /* fkey(max coord)        */

/* order-preserving float<->uint key */
__device__ __forceinline__ unsigned int fkey(float f) {
    unsigned int u = __float_as_uint(f);
    return (u & 0x80000000u) ? ~u : (u | 0x80000000u);
}
__device__ __forceinline__ float finv(unsigned int k) {
    unsigned int u = (k & 0x80000000u) ? (k ^ 0x80000000u) : ~k;
    return __uint_as_float(u);
}

/* ------------------------------ init ------------------------------------ */
__global__ void k_init() {
    int t = blockIdx.x * blockDim.x + threadIdx.x;
    int stride = gridDim.x * blockDim.x;
    if (t < B) { g_cnt[t] = 0; g_maxck[t] = 0u; }
    unsigned int* h = &g_hist[0][0];
    for (int i = t; i < B * HBINS; i += stride) h[i] = 0;
    unsigned int* fo = &g_binoff[0][0];
    for (int i = t; i < B * HBINS; i += stride) fo[i] = 0;
    unsigned int* fh = &g_fhist[0][0];
    for (int i = t; i < B * FBINS; i += stride) fh[i] = 0;
}

/* ------------- pass 1: fused speculative collect + fine hist ------------ */
__device__ __forceinline__ void proc_elem(float val, unsigned int eidx, int b) {
    if (val >= SPEC_F) {
        unsigned int key = __float_as_uint(val) | 0x80000000u; /* val>0 */
        unsigned int bin = (key - KEY0) >> HSHIFT;
        if (bin > HBINS - 1) bin = HBINS - 1;
        atomicAdd(&g_hist[b][bin], 1u);
        int pos = atomicAdd(&g_cnt[b], 1);
        if (pos < CAND_CAP)
            g_cand[b][pos] =
                ((unsigned long long)key << 32) | (0xFFFFFFFFu - eidx);
    }
}
__device__ __forceinline__ void proc_vec(float4 v, unsigned int i, int b) {
    unsigned int base = 4u * i;
    proc_elem(v.x, base + 0u, b);
    proc_elem(v.y, base + 1u, b);
    proc_elem(v.z, base + 2u, b);
    proc_elem(v.w, base + 3u, b);
}

__global__ void __launch_bounds__(256) k_main(const float* __restrict__ cls) {
    const int b = blockIdx.y;
    const float4* __restrict__ p = (const float4*)(cls + (size_t)b * NN);
    const unsigned int i0 = blockIdx.x * 1024u + threadIdx.x;
    float4 v0, v1, v2, v3;
    const float4 neg = make_float4(-1e30f, -1e30f, -1e30f, -1e30f);
    if ((blockIdx.x + 1) * 1024u <= (unsigned)N4) {
        v0 = p[i0];
        v1 = p[i0 + 256];
        v2 = p[i0 + 512];
        v3 = p[i0 + 768];
    } else {
        v0 = (i0       < (unsigned)N4) ? p[i0]       : neg;
        v1 = (i0 + 256 < (unsigned)N4) ? p[i0 + 256] : neg;
        v2 = (i0 + 512 < (unsigned)N4) ? p[i0 + 512] : neg;
        v3 = (i0 + 768 < (unsigned)N4) ? p[i0 + 768] : neg;
    }
    float m0 = fmaxf(fmaxf(v0.x, v0.y), fmaxf(v0.z, v0.w));
    float m1 = fmaxf(fmaxf(v1.x, v1.y), fmaxf(v1.z, v1.w));
    float m2 = fmaxf(fmaxf(v2.x, v2.y), fmaxf(v2.z, v2.w));
    float m3 = fmaxf(fmaxf(v3.x, v3.y), fmaxf(v3.z, v3.w));
    float m = fmaxf(fmaxf(m0, m1), fmaxf(m2, m3));
    if (m >= SPEC_F) {  /* ~2% of threads */
        proc_vec(v0, i0, b);
        proc_vec(v1, i0 + 256, b);
        proc_vec(v2, i0 + 512, b);
        proc_vec(v3, i0 + 768, b);
    }
}

/* ------- pass 2: exact threshold + descending prefix (block scan) ------- */
__global__ void __launch_bounds__(HBINS) k_thresh() {
    const int b = blockIdx.x;
    const int tid = threadIdx.x;
    __shared__ unsigned int wsum[32], woff[32], wmax[32];
    __shared__ int rT;
    __shared__ unsigned int totGe;

    /* d[r] = hist in descending-key order */
    unsigned int v = g_hist[b][HBINS - 1 - tid];
    unsigned int lane = tid & 31u, w = tid >> 5;
    unsigned int incl = v;
    #pragma unroll
    for (int o = 1; o < 32; o <<= 1) {
        unsigned int t = __shfl_up_sync(0xffffffffu, incl, o);
        if (lane >= (unsigned)o) incl += t;
    }
    if (lane == 31) wsum[w] = incl;
    if (tid == 0) { rT = -1; totGe = 0; }
    __syncthreads();
    if (tid == 0) {
        unsigned int acc = 0;
        for (int i = 0; i < 32; i++) { woff[i] = acc; acc += wsum[i]; }
    }
    __syncthreads();
    unsigned int excl = woff[w] + incl - v;
    g_binstart[b][HBINS - 1 - tid] = excl;
    if (v > 0 && excl < TOPK && excl + v >= TOPK) { rT = tid; totGe = excl + v; }
    __syncthreads();
    int r = rT;
    /* max bin count over relevant bins (r' <= rT) */
    unsigned int mv = (r >= 0 && tid <= r) ? v : 0;
    #pragma unroll
    for (int o = 16; o > 0; o >>= 1)
        mv = max(mv, __shfl_down_sync(0xffffffffu, mv, o));
    if (lane == 0) wmax[w] = mv;
    __syncthreads();
    if (tid == 0) {
        unsigned int mb = 0;
        for (int i = 0; i < 32; i++) mb = max(mb, wmax[i]);
        int cnt = g_cnt[b];
        int ok = (r >= 0) && (cnt <= CAND_CAP) && (totGe <= SORT_CAP) &&
                 (mb <= BINMAX);
        g_ok[b] = ok;
        if (ok) {
            int binT = HBINS - 1 - r;
            g_T[b] = binT;
            g_thresh[b] = KEY0 + ((unsigned int)binT << HSHIFT);
        }
    }
}

/* ---------------- fallback chain (early-exits when spec ok) -------------- */
__global__ void k_fb_hist(const float* __restrict__ cls) {
    const int b = blockIdx.y;
    if (g_ok[b]) return;
    __shared__ unsigned int h[FBINS];
    for (int i = threadIdx.x; i < FBINS; i += blockDim.x) h[i] = 0;
    __syncthreads();
    const float4* p = (const float4*)(cls + (size_t)b * NN);
    for (int i = blockIdx.x * blockDim.x + threadIdx.x; i < N4;
         i += gridDim.x * blockDim.x) {
        float4 v = p[i];
        atomicAdd(&h[fkey(v.x) >> 20], 1u);
        atomicAdd(&h[fkey(v.y) >> 20], 1u);
        atomicAdd(&h[fkey(v.z) >> 20], 1u);
        atomicAdd(&h[fkey(v.w) >> 20], 1u);
    }
    __syncthreads();
    for (int i = threadIdx.x; i < FBINS; i += blockDim.x)
        if (h[i]) atomicAdd(&g_fhist[b][i], h[i]);
}

__global__ void k_fb_thresh() {
    const int b = blockIdx.x;
    if (g_ok[b]) return;
    __shared__ unsigned int h[FBINS];
    for (int i = threadIdx.x; i < FBINS; i += blockDim.x) h[i] = g_fhist[b][i];
    __syncthreads();
    if (threadIdx.x == 0) {
        unsigned int acc = 0;
        int T = 0;
        for (int bin = FBINS - 1; bin >= 0; bin--) {
            acc += h[bin];
            if (acc >= TOPK) { T = bin; break; }
        }
        g_thresh[b] = ((unsigned int)T) << 20;
        g_cnt[b] = 0;
    }
}

__global__ void k_fb_collect(const float* __restrict__ cls) {
    const int b = blockIdx.y;
    if (g_ok[b]) return;
    const unsigned int th = g_thresh[b];
    const float4* p = (const float4*)(cls + (size_t)b * NN);
    for (int i = blockIdx.x * blockDim.x + threadIdx.x; i < N4;
         i += gridDim.x * blockDim.x) {
        float4 v = p[i];
        unsigned int base = 4u * (unsigned int)i;
        unsigned int k0 = fkey(v.x), k1 = fkey(v.y), k2 = fkey(v.z), k3 = fkey(v.w);
        if (k0 >= th) {
            int pos = atomicAdd(&g_cnt[b], 1);
            if (pos < CAND_CAP)
                g_cand[b][pos] = ((unsigned long long)k0 << 32) | (0xFFFFFFFFu - (base + 0u));
        }
        if (k1 >= th) {
            int pos = atomicAdd(&g_cnt[b], 1);
            if (pos < CAND_CAP)
                g_cand[b][pos] = ((unsigned long long)k1 << 32) | (0xFFFFFFFFu - (base + 1u));
        }
        if (k2 >= th) {
            int pos = atomicAdd(&g_cnt[b], 1);
            if (pos < CAND_CAP)
                g_cand[b][pos] = ((unsigned long long)k2 << 32) | (0xFFFFFFFFu - (base + 2u));
        }
        if (k3 >= th) {
            int pos = atomicAdd(&g_cnt[b], 1);
            if (pos < CAND_CAP)
                g_cand[b][pos] = ((unsigned long long)k3 << 32) | (0xFFFFFFFFu - (base + 3u));
        }
    }
}

/* fallback sort: single-block bitonic (only when spec path failed) */
__global__ void k_fb_sort() {
    extern __shared__ unsigned long long s[];
    const int b = blockIdx.x;
    if (g_ok[b]) return;
    const int tid = threadIdx.x;
    __shared__ int scnt;
    if (tid == 0) scnt = 0;
    __syncthreads();
    int cnt = g_cnt[b];
    if (cnt > CAND_CAP) cnt = CAND_CAP;
    const unsigned int th = g_thresh[b];
    for (int i = tid; i < cnt; i += blockDim.x) {
        unsigned long long kv = g_cand[b][i];
        if ((unsigned int)(kv >> 32) >= th) {
            int pos = atomicAdd(&scnt, 1);
            if (pos < SORT_CAP) s[pos] = kv;
        }
    }
    __syncthreads();
    int c2 = scnt;
    if (c2 > SORT_CAP) c2 = SORT_CAP;
    const int nn = (c2 <= 8192) ? 8192 : SORT_CAP;
    for (int i = c2 + tid; i < nn; i += blockDim.x) s[i] = 0ULL;
    __syncthreads();
    for (unsigned int k = 2; k <= (unsigned int)nn; k <<= 1) {
        for (unsigned int j = k >> 1; j > 0; j >>= 1) {
            for (int i = tid; i < nn; i += blockDim.x) {
                unsigned int ixj = (unsigned int)i ^ j;
                if (ixj > (unsigned int)i) {
                    bool up = ((i & k) == 0);
                    unsigned long long a = s[i], c = s[ixj];
                    bool sw = up ? (a < c) : (a > c);
                    if (sw) { s[i] = c; s[ixj] = a; }
                }
            }
            __syncthreads();
        }
    }
    for (int i = tid; i < TOPK; i += blockDim.x) g_sorted[b][i] = s[i];
}

/* ------------- pass 3a: scatter candidates into bin slots ---------------- */
__global__ void k_scatter() {
    const int b = blockIdx.y;
    if (!g_ok[b]) return;
    int cnt = g_cnt[b];
    if (cnt > CAND_CAP) cnt = CAND_CAP;
    const unsigned int th = g_thresh[b];
    const int stride = gridDim.x * blockDim.x;
    for (int i = blockIdx.x * blockDim.x + threadIdx.x; i < cnt; i += stride) {
        unsigned long long kv = g_cand[b][i];
        unsigned int key = (unsigned int)(kv >> 32);
        if (key >= th) {
            unsigned int bin = (key - KEY0) >> HSHIFT;
            if (bin > HBINS - 1) bin = HBINS - 1;
            unsigned int pos = g_binstart[b][bin] + atomicAdd(&g_binoff[b][bin], 1u);
            g_sorted[b][pos] = kv;
        }
    }
}

/* ------------- pass 3b: per-bin small bitonic sorts ---------------------- */
__global__ void __launch_bounds__(128) k_binsort() {
    const int bin = blockIdx.x;
    const int b = blockIdx.y;
    if (!g_ok[b]) return;
    if (bin < g_T[b]) return;
    const unsigned int c = g_hist[b][bin];
    if (c == 0) return;
    const unsigned int start = g_binstart[b][bin];
    __shared__ unsigned long long s[BINMAX];
    unsigned int n = 1;
    while (n < c) n <<= 1;
    const int tid = threadIdx.x;
    for (unsigned int i = tid; i < n; i += 128)
        s[i] = (i < c) ? g_sorted[b][start + i] : 0ULL;
    __syncthreads();
    for (unsigned int k = 2; k <= n; k <<= 1) {
        for (unsigned int j = k >> 1; j > 0; j >>= 1) {
            for (unsigned int i = tid; i < n; i += 128) {
                unsigned int ixj = i ^ j;
                if (ixj > i) {
                    bool up = ((i & k) == 0);
                    unsigned long long a = s[i], cc = s[ixj];
                    bool sw = up ? (a < cc) : (a > cc);
                    if (sw) { s[i] = cc; s[ixj] = a; }
                }
            }
            __syncthreads();
        }
    }
    for (unsigned int i = tid; i < c; i += 128) g_sorted[b][start + i] = s[i];
}

/* ------------------ pass 4: decode top-5000 + maxc ----------------------- */
__global__ void __launch_bounds__(256) k_decode(const float* __restrict__ box_out,
                                                const float* __restrict__ anchors) {
    const int b = blockIdx.y;
    const int i = blockIdx.x * 256 + threadIdx.x;
    float localmax = -1e30f;
    if (i < TOPK) {
        unsigned long long kv = g_sorted[b][i];
        if (kv == 0ULL) {
            g_boxes[b][i] = make_float4(0.f, 0.f, 0.f, 0.f);
            g_scores[b][i] = 0.f;
            g_cls[b][i] = 0;
        } else {
            unsigned int key = (unsigned int)(kv >> 32);
            unsigned int idx = 0xFFFFFFFFu - (unsigned int)(kv & 0xFFFFFFFFu);
            float val = finv(key);
            unsigned int a = idx / (unsigned int)C;
            int cidx = (int)(idx - a * (unsigned int)C);
            float4 rc = ((const float4*)box_out)[(size_t)b * A + a];
            float4 an = ((const float4*)anchors)[a];
            float ycA = (an.x + an.z) * 0.5f;
            float xcA = (an.y + an.w) * 0.5f;
            float ha = an.z - an.x;
            float wa = an.w - an.y;
            float w = expf(rc.w) * wa;
            float h = expf(rc.z) * ha;
            float yc = rc.x * ha + ycA;
            float xc = rc.y * wa + xcA;
            float4 box = make_float4(xc - w * 0.5f, yc - h * 0.5f,
                                     xc + w * 0.5f, yc + h * 0.5f);
            g_boxes[b][i] = box;
            g_scores[b][i] = 1.f / (1.f + expf(-val));
            g_cls[b][i] = cidx;
            localmax = fmaxf(fmaxf(box.x, box.y), fmaxf(box.z, box.w));
        }
    }
    /* block max -> global atomic on order-preserving key */
    __shared__ float red[256];
    red[threadIdx.x] = localmax;
    __syncthreads();
    for (int off = 128; off > 0; off >>= 1) {
        if (threadIdx.x < off)
            red[threadIdx.x] = fmaxf(red[threadIdx.x], red[threadIdx.x + off]);
        __syncthreads();
    }
    if (threadIdx.x == 0) atomicMax(&g_maxck[b], fkey(red[0]));
}

/* ---------------------- pass 5: greedy NMS + output ---------------------- */
__global__ void k_nms(const float* __restrict__ img_scale, float* __restrict__ out) {
    const int b = blockIdx.x;
    const int l = threadIdx.x; /* one warp per image */
    __shared__ float4 skb[MAXOUT + 32];
    __shared__ float ska[MAXOUT + 32];
    __shared__ float4 st_box[64];
    __shared__ float st_sc[64];
    __shared__ int st_cl[64];

    const float maxc1 = finv(g_maxck[b]) + 1.0f;
    const float scale = img_scale[b];
    int K = 0;

    for (int base = 0; base < TOPK && K < MAXOUT; base += 64) {
        int m = TOPK - base;
        if (m > 64) m = 64;
        for (int t = l; t < m; t += 32) {
            st_box[t] = g_boxes[b][base + t];
            st_sc[t] = g_scores[b][base + t];
            st_cl[t] = g_cls[b][base + t];
        }
        __syncwarp();
        for (int ii = 0; ii < m; ii++) {
            if (K >= MAXOUT) break;
            float4 bx = st_box[ii];
            int cidx = st_cl[ii];
            float off = (float)cidx * maxc1;
            float4 nb = make_float4(bx.x + off, bx.y + off, bx.z + off, bx.w + off);
            float areaC = (nb.z - nb.x) * (nb.w - nb.y);
            bool ov = false;
            for (int sidx = l; sidx < K; sidx += 32) {
                float4 kb = skb[sidx];
                float w = fminf(nb.z, kb.z) - fmaxf(nb.x, kb.x);
                float h = fminf(nb.w, kb.w) - fmaxf(nb.y, kb.y);
                w = fmaxf(w, 0.f);
                h = fmaxf(h, 0.f);
                float inter = w * h;
                if (inter > 0.f) {
                    float uni = areaC + ska[sidx] - inter;
                    if (inter / uni > IOU_T) ov = true;
                }
            }
            if (!__any_sync(0xffffffffu, ov)) {
                if (l == 0) {
                    skb[K] = nb;
                    ska[K] = areaC;
                    float* o = out + ((size_t)b * MAXOUT + K) * 6;
                    o[0] = bx.x * scale;
                    o[1] = bx.y * scale;
                    o[2] = bx.z * scale;
                    o[3] = bx.w * scale;
                    o[4] = st_sc[ii];
                    o[5] = (float)(cidx + 1);
                }
                K++;
                __syncwarp();
            }
        }
        __syncwarp();
    }
    for (int r = l; r < MAXOUT; r += 32) {
        if (r >= K) {
            float* o = out + ((size_t)b * MAXOUT + r) * 6;
            o[0] = 0.f; o[1] = 0.f; o[2] = 0.f; o[3] = 0.f;
            o[4] = 0.f; o[5] = -1.f;
        }
    }
}

/* ------------------------------ launcher -------------------------------- */
extern "C" void kernel_launch(void* const* d_in, const int* in_sizes, int n_in,
                              void* d_out, int out_size) {
    const float* cls = nullptr;
    const float* box = nullptr;
    const float* anc = nullptr;
    const float* scl = nullptr;
    for (int i = 0; i < n_in; i++) {
        long long sz = in_sizes[i];
        if (sz == (long long)B * NN) cls = (const float*)d_in[i];
        else if (sz == (long long)B * A * 4) box = (const float*)d_in[i];
        else if (sz == (long long)A * 4) anc = (const float*)d_in[i];
        else if (sz == B) scl = (const float*)d_in[i];
    }
    float* out = (float*)d_out;

    static bool attr_set = false;
    if (!attr_set) {
        cudaFuncSetAttribute(k_fb_sort,
                             cudaFuncAttributeMaxDynamicSharedMemorySize,
                             SORT_CAP * (int)sizeof(unsigned long long));
        attr_set = true;
    }

    k_init<<<16, 1024>>>();
    {
        dim3 grid((N4 + 1023) / 1024, B);
        k_main<<<grid, 256>>>(cls);
    }
    k_thresh<<<B, HBINS>>>();
    {
        dim3 grid(64, B);
        k_fb_hist<<<grid, 256>>>(cls);
    }
    k_fb_thresh<<<B, 1024>>>();
    {
        dim3 grid(64, B);
        k_fb_collect<<<grid, 256>>>(cls);
    }
    k_fb_sort<<<B, 1024, SORT_CAP * sizeof(unsigned long long)>>>();
    {
        dim3 grid(16, B);
        k_scatter<<<grid, 256>>>();
    }
    {
        dim3 grid(HBINS, B);
        k_binsort<<<grid, 128>>>();
    }
    {
        dim3 grid((TOPK + 255) / 256, B);
        k_decode<<<grid, 256>>>(box, anc);
    }
    k_nms<<<B, 32>>>(scl, out);
}